// round 1
// baseline (speedup 1.0000x reference)
#include <cuda_runtime.h>

#define V 500000
#define NF 1000000
#define KDEG 7

// Scalar loss accumulators (zeroed each call by tile_kernel thread 0,
// which completes before loss_kernel runs — same stream).
__device__ float g_lap_sum;
__device__ float g_hex_sum;

// ---------------------------------------------------------------------------
// Kernel A: build verts = vertices + center, write 4 tiled copies to d_out;
// convert faces (int32) -> float and write 4 tiled copies. Zero accumulators.
// Layout of d_out (float32):
//   [0,            6,000,000)  : vertices_rep  (4 copies of V*3)
//   [6,000,000,   18,000,000)  : faces_rep     (4 copies of NF*3)
//   [18,000,000,  18,000,004)  : lap_loss, hex_loss, 0, 0
// ---------------------------------------------------------------------------
__global__ void tile_kernel(const float* __restrict__ vertices,
                            const float* __restrict__ center,
                            const int*   __restrict__ faces,
                            float* __restrict__ out)
{
    const int VN = V * 3;        // 1,500,000
    const int FN = NF * 3;       // 3,000,000
    int j = blockIdx.x * blockDim.x + threadIdx.x;

    if (j == 0) { g_lap_sum = 0.0f; g_hex_sum = 0.0f; }

    if (j < VN) {
        float v = vertices[j] + __ldg(center + (j % 3));
        out[j]          = v;
        out[j + VN]     = v;
        out[j + 2 * VN] = v;
        out[j + 3 * VN] = v;
    } else if (j < VN + FN) {
        int idx = j - VN;
        float f = (float)__ldg(faces + idx);
        float* fo = out + 4 * VN;  // 6,000,000
        fo[idx]          = f;
        fo[idx + FN]     = f;
        fo[idx + 2 * FN] = f;
        fo[idx + 3 * FN] = f;
    }
}

__inline__ __device__ float warp_sum(float v) {
    #pragma unroll
    for (int o = 16; o > 0; o >>= 1) v += __shfl_down_sync(0xffffffffu, v, o);
    return v;
}

// ---------------------------------------------------------------------------
// Kernel B: fused SpMV + losses. One thread per vertex row.
//  - lap: binary-search the sorted off-diagonal row segment [start,end),
//    accumulate v * verts[col], add analytic diagonal (-verts[i]),
//    take the row L2 norm.
//  - hex: row i owns k entries [7i, 7i+7); accumulate, take sum of squares.
//  - block-reduce both, one atomicAdd per block per loss.
// verts are gathered from the first tiled copy in d_out.
// ---------------------------------------------------------------------------
__global__ void loss_kernel(const float* __restrict__ verts,   // d_out base
                            const int*   __restrict__ lap_rows,
                            const int*   __restrict__ lap_cols,
                            const float* __restrict__ lap_vals,
                            const int*   __restrict__ k_cols,
                            const float* __restrict__ k_vals,
                            int nnz_off)
{
    int i = blockIdx.x * blockDim.x + threadIdx.x;
    float lap_n = 0.0f, hex_s = 0.0f;

    if (i < V) {
        // lower_bound(lap_rows, i) over [0, nnz_off)
        int lo = 0, hi = nnz_off;
        while (lo < hi) {
            int mid = (lo + hi) >> 1;
            if (__ldg(lap_rows + mid) < i) lo = mid + 1; else hi = mid;
        }
        int start = lo;
        // lower_bound(lap_rows, i+1) over [start, nnz_off)
        hi = nnz_off;
        while (lo < hi) {
            int mid = (lo + hi) >> 1;
            if (__ldg(lap_rows + mid) < i + 1) lo = mid + 1; else hi = mid;
        }
        int end = lo;

        // diagonal entry value is -1 -> start from -verts[i]
        float ax = -__ldg(verts + 3 * i);
        float ay = -__ldg(verts + 3 * i + 1);
        float az = -__ldg(verts + 3 * i + 2);

        for (int e = start; e < end; e++) {
            int   c = __ldg(lap_cols + e);
            float v = __ldg(lap_vals + e);
            ax += v * __ldg(verts + 3 * c);
            ay += v * __ldg(verts + 3 * c + 1);
            az += v * __ldg(verts + 3 * c + 2);
        }
        lap_n = sqrtf(ax * ax + ay * ay + az * az);

        float kx = 0.0f, ky = 0.0f, kz = 0.0f;
        int b = i * KDEG;
        #pragma unroll
        for (int j = 0; j < KDEG; j++) {
            int   c = __ldg(k_cols + b + j);
            float v = __ldg(k_vals + b + j);
            kx += v * __ldg(verts + 3 * c);
            ky += v * __ldg(verts + 3 * c + 1);
            kz += v * __ldg(verts + 3 * c + 2);
        }
        hex_s = kx * kx + ky * ky + kz * kz;
    }

    // block reduction (256 threads = 8 warps)
    __shared__ float s_lap[8];
    __shared__ float s_hex[8];
    int lane = threadIdx.x & 31;
    int wid  = threadIdx.x >> 5;

    lap_n = warp_sum(lap_n);
    hex_s = warp_sum(hex_s);
    if (lane == 0) { s_lap[wid] = lap_n; s_hex[wid] = hex_s; }
    __syncthreads();
    if (wid == 0) {
        float a = (lane < 8) ? s_lap[lane] : 0.0f;
        float h = (lane < 8) ? s_hex[lane] : 0.0f;
        a = warp_sum(a);
        h = warp_sum(h);
        if (lane == 0) {
            atomicAdd(&g_lap_sum, a);
            atomicAdd(&g_hex_sum, h);
        }
    }
}

// ---------------------------------------------------------------------------
// Kernel C: write the 4 trailing scalars.
// ---------------------------------------------------------------------------
__global__ void scalar_kernel(float* __restrict__ out, int scalar_off)
{
    out[scalar_off + 0] = g_lap_sum * (1.0f / (float)V);
    out[scalar_off + 1] = g_hex_sum * (1.0f / (float)V);
    out[scalar_off + 2] = 0.0f;
    out[scalar_off + 3] = 0.0f;
}

extern "C" void kernel_launch(void* const* d_in, const int* in_sizes, int n_in,
                              void* d_out, int out_size)
{
    const float* vertices = (const float*)d_in[0];
    const float* center   = (const float*)d_in[1];
    const int*   lap_rows = (const int*)  d_in[2];
    const int*   lap_cols = (const int*)  d_in[3];
    const float* lap_vals = (const float*)d_in[4];
    // d_in[5] = k_rows (structurally repeat(arange(V), 7) -> unused)
    const int*   k_cols   = (const int*)  d_in[6];
    const float* k_vals   = (const float*)d_in[7];
    const int*   faces    = (const int*)  d_in[8];
    // d_in[9] = total_num (fixed = 4)

    float* out = (float*)d_out;

    int nnz     = in_sizes[2];        // includes V diagonal entries appended last
    int nnz_off = nnz - V;            // sorted off-diagonal segment length

    // A: tiling + verts materialization + accumulator zeroing
    {
        int total = V * 3 + NF * 3;   // 4,500,000
        int threads = 256;
        int blocks = (total + threads - 1) / threads;
        tile_kernel<<<blocks, threads>>>(vertices, center, faces, out);
    }

    // B: fused SpMV + loss reduction (gathers verts from out[0 .. V*3))
    {
        int threads = 256;
        int blocks = (V + threads - 1) / threads;
        loss_kernel<<<blocks, threads>>>(out, lap_rows, lap_cols, lap_vals,
                                         k_cols, k_vals, nnz_off);
    }

    // C: trailing scalars (last 4 elements of the output)
    scalar_kernel<<<1, 1>>>(out, out_size - 4);
}

// round 2
// speedup vs baseline: 1.2537x; 1.2537x over previous
#include <cuda_runtime.h>

#define V 500000
#define NF 1000000
#define KDEG 7
#define VN (V * 3)      // 1,500,000
#define FN (NF * 3)     // 3,000,000

// Scalar loss accumulators (zeroed by setup_kernel thread 0).
__device__ float g_lap_sum;
__device__ float g_hex_sum;

// CSR row pointers for the sorted off-diagonal lap segment.
__device__ int g_row_start[V + 1];

// Padded verts: one 16B-aligned float4 per vertex -> 1 LDG.128 per gather.
__device__ float4 g_pad[V];

// ---------------------------------------------------------------------------
// Kernel A (vectorized): three sections in one grid.
//   [0, V)                 : write padded verts scratch g_pad[i]
//   [V, V+VN/4)            : verts+center tiled x4 into d_out, float4 lanes
//   [V+VN/4, V+VN/4+FN/4)  : faces -> float tiled x4, int4->float4 lanes
// ---------------------------------------------------------------------------
__global__ void setup_kernel(const float* __restrict__ vertices,
                             const float* __restrict__ center,
                             const int*   __restrict__ faces,
                             float* __restrict__ out)
{
    int t = blockIdx.x * blockDim.x + threadIdx.x;
    float c0 = __ldg(center), c1 = __ldg(center + 1), c2 = __ldg(center + 2);

    if (t == 0) { g_lap_sum = 0.0f; g_hex_sum = 0.0f; }

    if (t < V) {
        float x = __ldg(vertices + 3 * t)     + c0;
        float y = __ldg(vertices + 3 * t + 1) + c1;
        float z = __ldg(vertices + 3 * t + 2) + c2;
        g_pad[t] = make_float4(x, y, z, 0.0f);
    } else if (t < V + VN / 4) {
        int j = t - V;
        const float4* v4 = (const float4*)vertices;
        float4 vv = v4[j];
        // element 4j has component (4j)%3 == j%3
        int m0 = j % 3;
        int m1 = (m0 + 1 == 3) ? 0 : m0 + 1;
        int m2 = (m1 + 1 == 3) ? 0 : m1 + 1;
        float a0 = (m0 == 0) ? c0 : ((m0 == 1) ? c1 : c2);
        float a1 = (m1 == 0) ? c0 : ((m1 == 1) ? c1 : c2);
        float a2 = (m2 == 0) ? c0 : ((m2 == 1) ? c1 : c2);
        vv.x += a0; vv.y += a1; vv.z += a2; vv.w += a0;  // (m2+1)%3 == m0
        float4* o4 = (float4*)out;
        const int Q = VN / 4;
        o4[j] = vv; o4[j + Q] = vv; o4[j + 2 * Q] = vv; o4[j + 3 * Q] = vv;
    } else if (t < V + VN / 4 + FN / 4) {
        int j = t - V - VN / 4;
        const int4* f4 = (const int4*)faces;
        int4 f = f4[j];
        float4 ff = make_float4((float)f.x, (float)f.y, (float)f.z, (float)f.w);
        float4* fo = (float4*)(out + 4 * VN);
        const int Q = FN / 4;
        fo[j] = ff; fo[j + Q] = ff; fo[j + 2 * Q] = ff; fo[j + 3 * Q] = ff;
    }
}

// ---------------------------------------------------------------------------
// Kernel R: build CSR row pointers from the sorted row array.
// Handles empty rows (gap fill) and head/tail.
// ---------------------------------------------------------------------------
__global__ void rowptr_kernel(const int* __restrict__ lap_rows, int nnz_off)
{
    int e = blockIdx.x * blockDim.x + threadIdx.x;
    if (e >= nnz_off) return;
    int cur = __ldg(lap_rows + e);
    if (e == 0) {
        for (int r = 0; r <= cur; r++) g_row_start[r] = 0;
    } else {
        int prev = __ldg(lap_rows + e - 1);
        if (cur != prev) {
            for (int r = prev + 1; r <= cur; r++) g_row_start[r] = e;
        }
    }
    if (e == nnz_off - 1) {
        for (int r = cur + 1; r <= V; r++) g_row_start[r] = nnz_off;
    }
}

__inline__ __device__ float warp_sum(float v) {
    #pragma unroll
    for (int o = 16; o > 0; o >>= 1) v += __shfl_down_sync(0xffffffffu, v, o);
    return v;
}

// ---------------------------------------------------------------------------
// Kernel B: fused SpMV + losses, one thread per row, CSR pointers,
// float4 gathers from g_pad.
// ---------------------------------------------------------------------------
__global__ void loss_kernel(const int*   __restrict__ lap_cols,
                            const float* __restrict__ lap_vals,
                            const int*   __restrict__ k_cols,
                            const float* __restrict__ k_vals)
{
    int i = blockIdx.x * blockDim.x + threadIdx.x;
    float lap_n = 0.0f, hex_s = 0.0f;

    if (i < V) {
        int s = g_row_start[i];
        int e = g_row_start[i + 1];

        float4 me = g_pad[i];
        float ax = -me.x, ay = -me.y, az = -me.z;  // analytic diagonal (-1)

        for (int q = s; q < e; q++) {
            int   c = __ldg(lap_cols + q);
            float v = __ldg(lap_vals + q);
            float4 p = g_pad[c];
            ax += v * p.x; ay += v * p.y; az += v * p.z;
        }
        lap_n = sqrtf(ax * ax + ay * ay + az * az);

        float kx = 0.0f, ky = 0.0f, kz = 0.0f;
        int b = i * KDEG;
        #pragma unroll
        for (int j = 0; j < KDEG; j++) {
            int   c = __ldg(k_cols + b + j);
            float v = __ldg(k_vals + b + j);
            float4 p = g_pad[c];
            kx += v * p.x; ky += v * p.y; kz += v * p.z;
        }
        hex_s = kx * kx + ky * ky + kz * kz;
    }

    __shared__ float s_lap[8];
    __shared__ float s_hex[8];
    int lane = threadIdx.x & 31;
    int wid  = threadIdx.x >> 5;

    lap_n = warp_sum(lap_n);
    hex_s = warp_sum(hex_s);
    if (lane == 0) { s_lap[wid] = lap_n; s_hex[wid] = hex_s; }
    __syncthreads();
    if (wid == 0) {
        float a = (lane < 8) ? s_lap[lane] : 0.0f;
        float h = (lane < 8) ? s_hex[lane] : 0.0f;
        a = warp_sum(a);
        h = warp_sum(h);
        if (lane == 0) {
            atomicAdd(&g_lap_sum, a);
            atomicAdd(&g_hex_sum, h);
        }
    }
}

// ---------------------------------------------------------------------------
// Kernel C: trailing scalars.
// ---------------------------------------------------------------------------
__global__ void scalar_kernel(float* __restrict__ out, int scalar_off)
{
    out[scalar_off + 0] = g_lap_sum * (1.0f / (float)V);
    out[scalar_off + 1] = g_hex_sum * (1.0f / (float)V);
    out[scalar_off + 2] = 0.0f;
    out[scalar_off + 3] = 0.0f;
}

extern "C" void kernel_launch(void* const* d_in, const int* in_sizes, int n_in,
                              void* d_out, int out_size)
{
    const float* vertices = (const float*)d_in[0];
    const float* center   = (const float*)d_in[1];
    const int*   lap_rows = (const int*)  d_in[2];
    const int*   lap_cols = (const int*)  d_in[3];
    const float* lap_vals = (const float*)d_in[4];
    const int*   k_cols   = (const int*)  d_in[6];
    const float* k_vals   = (const float*)d_in[7];
    const int*   faces    = (const int*)  d_in[8];

    float* out = (float*)d_out;

    int nnz     = in_sizes[2];
    int nnz_off = nnz - V;   // sorted off-diagonal segment (diag appended last)

    {   // A: scratch pad + tiled outputs (vectorized)
        int total = V + VN / 4 + FN / 4;   // 1,625,000
        setup_kernel<<<(total + 255) / 256, 256>>>(vertices, center, faces, out);
    }
    {   // R: CSR row pointers
        rowptr_kernel<<<(nnz_off + 255) / 256, 256>>>(lap_rows, nnz_off);
    }
    {   // B: fused SpMV + losses
        loss_kernel<<<(V + 255) / 256, 256>>>(lap_cols, lap_vals, k_cols, k_vals);
    }
    scalar_kernel<<<1, 1>>>(out, out_size - 4);
}